// round 2
// baseline (speedup 1.0000x reference)
#include <cuda_runtime.h>
#include <math.h>

#define N 1024
#define C 128
#define H 4
#define HD 32
#define HID 64
#define TI 16
#define TJ 16

// ---- scratch (device globals; no allocation in kernel_launch) ----
__device__ float  g_q[N * C];
__device__ float  g_k[N * C];
__device__ float  g_v[N * C];
__device__ float4 g_A4[N * HID];     // [i][m] -> {A[i,0,m],A[i,1,m],A[i,2,m],A[i,3,m]}
__device__ float  g_qb2[N * H];      // q[i,h] . b2[h*HD:]
__device__ float  g_Pib[N * HID];    // pos[i]@W1 + b1
__device__ float  g_Pj[N * HID];     // pos[j]@W1
__device__ float  g_scores[(size_t)H * N * N];  // 16MB, L2-resident

// ---------------------------------------------------------------
// K1: q = x@Wq+bq, k = y@Wk+bk, v = y@Wv+bv
// grid (N, 3), block 128 (one thread per output column)
// ---------------------------------------------------------------
__global__ void qkv_kernel(const float* __restrict__ x, const float* __restrict__ y,
                           const float* __restrict__ Wq, const float* __restrict__ bq,
                           const float* __restrict__ Wk, const float* __restrict__ bk,
                           const float* __restrict__ Wv, const float* __restrict__ bv) {
    int n = blockIdx.x;
    int which = blockIdx.y;  // 0=q, 1=k, 2=v
    const float* in = (which == 0) ? x : y;
    const float* W  = (which == 0) ? Wq : (which == 1 ? Wk : Wv);
    const float* b  = (which == 0) ? bq : (which == 1 ? bk : bv);
    float* out      = (which == 0) ? g_q : (which == 1 ? g_k : g_v);

    __shared__ float xs[C];
    int c = threadIdx.x;
    xs[c] = in[n * C + c];
    __syncthreads();

    float acc = b[c];
#pragma unroll 16
    for (int kk = 0; kk < C; kk++)
        acc += xs[kk] * W[kk * C + c];
    out[n * C + c] = acc;
}

// ---------------------------------------------------------------
// K2: per-row precompute: A4[i][m], qb2[i][h], Pib[i][m], Pj[i][m]
// grid N, block 64 (one thread per m)
// ---------------------------------------------------------------
__global__ void prep_kernel(const float* __restrict__ pos,
                            const float* __restrict__ W1, const float* __restrict__ b1,
                            const float* __restrict__ W2, const float* __restrict__ b2) {
    int i = blockIdx.x;
    int m = threadIdx.x;  // 0..63

    __shared__ float qs[C];
    qs[m]      = g_q[i * C + m];
    qs[m + 64] = g_q[i * C + m + 64];
    __syncthreads();

    // A[i,h,m] = sum_d W2[m, h*HD+d] * q[i, h*HD+d]
    const float* w2row = W2 + m * C;
    float4 a = make_float4(0.f, 0.f, 0.f, 0.f);
#pragma unroll
    for (int d = 0; d < HD; d++) {
        a.x += w2row[0 * HD + d] * qs[0 * HD + d];
        a.y += w2row[1 * HD + d] * qs[1 * HD + d];
        a.z += w2row[2 * HD + d] * qs[2 * HD + d];
        a.w += w2row[3 * HD + d] * qs[3 * HD + d];
    }
    g_A4[i * HID + m] = a;

    // pos projection through W1 (W1 is [3][HID] row-major)
    float px = pos[i * 3 + 0], py = pos[i * 3 + 1], pz = pos[i * 3 + 2];
    float p1 = px * W1[m] + py * W1[HID + m] + pz * W1[2 * HID + m];
    g_Pj[i * HID + m]  = p1;
    g_Pib[i * HID + m] = p1 + b1[m];

    // qb2[i,h]
    if (m < H) {
        float s = 0.f;
#pragma unroll
        for (int d = 0; d < HD; d++) s += qs[m * HD + d] * b2[m * HD + d];
        g_qb2[i * H + m] = s;
    }
}

// ---------------------------------------------------------------
// K3: scores[h,i,j] = (q_i.k_j)/sqrt(HD) + sum_m relu(Pib_i[m]-Pj_j[m])*A[i,h,m]
//                     + qb2[i,h] - |pos_i - pos_j|
// grid (N/TJ, N/TI), block 256; one thread per (i,j) pair in a 16x16 tile
// ---------------------------------------------------------------
__global__ void __launch_bounds__(256) scores_kernel(const float* __restrict__ pos) {
    __shared__ __align__(16) float qs[TI][132];       // padded rows (132 % 4 == 0 for float4)
    __shared__ __align__(16) float ks[TJ][132];
    __shared__ float Pib_s[TI][HID + 1];
    __shared__ float Pj_s[TJ][HID + 1];
    __shared__ float4 A4_s[TI][HID + 2];
    __shared__ float pis[TI][3], pjs[TJ][3];
    __shared__ float qb2s[TI][4];

    int i0 = blockIdx.y * TI;
    int j0 = blockIdx.x * TJ;
    int tid = threadIdx.x;

    // cooperative tile loads
    for (int t = tid; t < TI * C; t += 256) {
        int r = t >> 7, c = t & 127;
        qs[r][c] = g_q[(i0 + r) * C + c];
        ks[r][c] = g_k[(j0 + r) * C + c];
    }
    for (int t = tid; t < TI * HID; t += 256) {
        int r = t >> 6, m = t & 63;
        Pib_s[r][m] = g_Pib[(i0 + r) * HID + m];
        Pj_s[r][m]  = g_Pj[(j0 + r) * HID + m];
        A4_s[r][m]  = g_A4[(i0 + r) * HID + m];
    }
    if (tid < TI) {
        pis[tid][0] = pos[(i0 + tid) * 3 + 0];
        pis[tid][1] = pos[(i0 + tid) * 3 + 1];
        pis[tid][2] = pos[(i0 + tid) * 3 + 2];
        pjs[tid][0] = pos[(j0 + tid) * 3 + 0];
        pjs[tid][1] = pos[(j0 + tid) * 3 + 1];
        pjs[tid][2] = pos[(j0 + tid) * 3 + 2];
    }
    if (tid < TI * H) {
        qb2s[tid >> 2][tid & 3] = g_qb2[(i0 + (tid >> 2)) * H + (tid & 3)];
    }
    __syncthreads();

    int il = tid >> 4;
    int jl = tid & 15;

    float dx = pis[il][0] - pjs[jl][0];
    float dy = pis[il][1] - pjs[jl][1];
    float dz = pis[il][2] - pjs[jl][2];
    float dist = sqrtf(dx * dx + dy * dy + dz * dz);

    // geometry MLP contribution per head
    float s0 = 0.f, s1 = 0.f, s2 = 0.f, s3 = 0.f;
#pragma unroll
    for (int m = 0; m < HID; m++) {
        float hm = fmaxf(Pib_s[il][m] - Pj_s[jl][m], 0.f);
        float4 a = A4_s[il][m];
        s0 += hm * a.x;
        s1 += hm * a.y;
        s2 += hm * a.z;
        s3 += hm * a.w;
    }

    const float inv_sqrt_hd = 0.17677669529663687f;  // 1/sqrt(32)
    int iglob = i0 + il, jglob = j0 + jl;
    float sgeom[4] = {s0, s1, s2, s3};

#pragma unroll
    for (int h = 0; h < H; h++) {
        float t = 0.f;
#pragma unroll
        for (int d = 0; d < HD; d += 4) {
            float4 qv = *(const float4*)&qs[il][h * HD + d];
            float4 kv = *(const float4*)&ks[jl][h * HD + d];
            t += qv.x * kv.x + qv.y * kv.y + qv.z * kv.z + qv.w * kv.w;
        }
        float sc = t * inv_sqrt_hd + sgeom[h] + qb2s[il][h] - dist;
        g_scores[((size_t)h * N + iglob) * N + jglob] = sc;
    }
}

// ---------------------------------------------------------------
// K4: softmax over j + out[i, h*HD+d] = sum_j p[j] * v[j, h*HD+d]
// grid (N/8, H), block 256: warp w handles row i0+w of head h
// ---------------------------------------------------------------
__global__ void __launch_bounds__(256) softmax_out_kernel(float* __restrict__ out) {
    int h = blockIdx.y;
    int i0 = blockIdx.x * 8;
    int warp = threadIdx.x >> 5, lane = threadIdx.x & 31;
    int i = i0 + warp;

    __shared__ float es[8][N + 1];  // padded to kill cross-warp bank conflicts

    const float* srow = g_scores + ((size_t)h * N + i) * N;

    float vals[32];
    float m = -INFINITY;
#pragma unroll
    for (int t = 0; t < 32; t++) {
        float s = srow[t * 32 + lane];
        vals[t] = s;
        m = fmaxf(m, s);
    }
#pragma unroll
    for (int o = 16; o; o >>= 1) m = fmaxf(m, __shfl_xor_sync(0xFFFFFFFFu, m, o));

    float sum = 0.f;
#pragma unroll
    for (int t = 0; t < 32; t++) {
        float e = __expf(vals[t] - m);
        es[warp][t * 32 + lane] = e;
        sum += e;
    }
#pragma unroll
    for (int o = 16; o; o >>= 1) sum += __shfl_xor_sync(0xFFFFFFFFu, sum, o);
    __syncwarp();

    // PV matvec: lane = output dim d within head
    const float* vcol = g_v + h * HD + lane;
    float a0 = 0.f, a1 = 0.f, a2 = 0.f, a3 = 0.f;
#pragma unroll 4
    for (int j = 0; j < N; j += 4) {
        a0 += es[warp][j + 0] * vcol[(j + 0) * C];
        a1 += es[warp][j + 1] * vcol[(j + 1) * C];
        a2 += es[warp][j + 2] * vcol[(j + 2) * C];
        a3 += es[warp][j + 3] * vcol[(j + 3) * C];
    }
    float acc = (a0 + a1) + (a2 + a3);
    out[i * C + h * HD + lane] = acc / sum;
}

// ---------------------------------------------------------------
extern "C" void kernel_launch(void* const* d_in, const int* in_sizes, int n_in,
                              void* d_out, int out_size) {
    (void)in_sizes; (void)n_in; (void)out_size;
    const float* x   = (const float*)d_in[0];
    const float* y   = (const float*)d_in[1];
    const float* pos = (const float*)d_in[2];
    const float* Wq  = (const float*)d_in[3];
    const float* bq  = (const float*)d_in[4];
    const float* Wk  = (const float*)d_in[5];
    const float* bk  = (const float*)d_in[6];
    const float* Wv  = (const float*)d_in[7];
    const float* bv  = (const float*)d_in[8];
    const float* W1  = (const float*)d_in[9];
    const float* b1  = (const float*)d_in[10];
    const float* W2  = (const float*)d_in[11];
    const float* b2  = (const float*)d_in[12];
    float* out = (float*)d_out;

    qkv_kernel<<<dim3(N, 3), 128>>>(x, y, Wq, bq, Wk, bk, Wv, bv);
    prep_kernel<<<N, 64>>>(pos, W1, b1, W2, b2);
    scores_kernel<<<dim3(N / TJ, N / TI), 256>>>(pos);
    softmax_out_kernel<<<dim3(N / 8, H), 256>>>(out);
}

// round 3
// speedup vs baseline: 1.0231x; 1.0231x over previous
#include <cuda_runtime.h>
#include <math.h>

#define N 1024
#define C 128
#define H 4
#define HD 32
#define HID 64
#define TI 16
#define TJ 64

// ---- scratch (device globals; no allocation in kernel_launch) ----
__device__ float  g_q[N * C];
__device__ float  g_k[N * C];
__device__ float  g_v[N * C];
__device__ float4 g_A4[N * HID];     // [i][m] -> {A[i,h=0..3,m]}
__device__ float  g_qb2[N * H];      // q[i,h] . b2[h*HD:]
__device__ float  g_Pib[N * HID];    // pos[i]@W1 + b1
__device__ float  g_Pj[N * HID];     // pos[j]@W1
__device__ float  g_scores[(size_t)H * N * N];  // 16MB, L2-resident

// ---------------------------------------------------------------
// K1: q = x@Wq+bq, k = y@Wk+bk, v = y@Wv+bv  (16 rows per block)
// grid (N/16, 3), block 128
// ---------------------------------------------------------------
__global__ void __launch_bounds__(128) qkv_kernel(
        const float* __restrict__ x, const float* __restrict__ y,
        const float* __restrict__ Wq, const float* __restrict__ bq,
        const float* __restrict__ Wk, const float* __restrict__ bk,
        const float* __restrict__ Wv, const float* __restrict__ bv) {
    int n0 = blockIdx.x * 16;
    int which = blockIdx.y;  // 0=q, 1=k, 2=v
    const float* in = (which == 0) ? x : y;
    const float* W  = (which == 0) ? Wq : (which == 1 ? Wk : Wv);
    const float* b  = (which == 0) ? bq : (which == 1 ? bk : bv);
    float* out      = (which == 0) ? g_q : (which == 1 ? g_k : g_v);

    __shared__ float xs[16][C];
    int c = threadIdx.x;
#pragma unroll
    for (int r = 0; r < 16; r++)
        xs[r][c] = in[(n0 + r) * C + c];
    __syncthreads();

    float acc[16];
    float bc = b[c];
#pragma unroll
    for (int r = 0; r < 16; r++) acc[r] = bc;

#pragma unroll 4
    for (int kk = 0; kk < C; kk++) {
        float w = W[kk * C + c];
#pragma unroll
        for (int r = 0; r < 16; r++)
            acc[r] += xs[r][kk] * w;
    }
#pragma unroll
    for (int r = 0; r < 16; r++)
        out[(n0 + r) * C + c] = acc[r];
}

// ---------------------------------------------------------------
// K2: per-row precompute: A4[i][m], qb2[i][h], Pib[i][m], Pj[i][m]
// grid N, block 64
// ---------------------------------------------------------------
__global__ void prep_kernel(const float* __restrict__ pos,
                            const float* __restrict__ W1, const float* __restrict__ b1,
                            const float* __restrict__ W2, const float* __restrict__ b2) {
    int i = blockIdx.x;
    int m = threadIdx.x;  // 0..63

    __shared__ float qs[C];
    qs[m]      = g_q[i * C + m];
    qs[m + 64] = g_q[i * C + m + 64];
    __syncthreads();

    const float* w2row = W2 + m * C;
    float4 a = make_float4(0.f, 0.f, 0.f, 0.f);
#pragma unroll
    for (int d = 0; d < HD; d++) {
        a.x += w2row[0 * HD + d] * qs[0 * HD + d];
        a.y += w2row[1 * HD + d] * qs[1 * HD + d];
        a.z += w2row[2 * HD + d] * qs[2 * HD + d];
        a.w += w2row[3 * HD + d] * qs[3 * HD + d];
    }
    g_A4[i * HID + m] = a;

    float px = pos[i * 3 + 0], py = pos[i * 3 + 1], pz = pos[i * 3 + 2];
    float p1 = px * W1[m] + py * W1[HID + m] + pz * W1[2 * HID + m];
    g_Pj[i * HID + m]  = p1;
    g_Pib[i * HID + m] = p1 + b1[m];

    if (m < H) {
        float s = 0.f;
#pragma unroll
        for (int d = 0; d < HD; d++) s += qs[m * HD + d] * b2[m * HD + d];
        g_qb2[i * H + m] = s;
    }
}

// ---------------------------------------------------------------
// K3: scores. Tile TI=16 x TJ=64, 256 threads, 4 pairs per thread
// (1 i x 4 contiguous j). PjT transposed in smem so one LDS.128
// serves 4 j. q tile pre-scaled by 1/sqrt(HD); qb2 folded into init.
// ---------------------------------------------------------------
struct ScoresSmem {
    float  qs[TI][132];        // q * inv_sqrt_hd
    float  ks[TJ][132];
    float  Pib[TI][HID];
    float  PjT[HID][TJ + 4];   // transposed: [m][j]
    float4 A4[TI][HID];
    float  pis[TI][3];
    float  pjs[TJ][3];
    float  qb2[TI][4];
};

__global__ void __launch_bounds__(256) scores_kernel(const float* __restrict__ pos) {
    extern __shared__ __align__(16) char s_raw[];
    ScoresSmem& s = *reinterpret_cast<ScoresSmem*>(s_raw);

    int i0 = blockIdx.y * TI;
    int j0 = blockIdx.x * TJ;
    int tid = threadIdx.x;
    const float inv_sqrt_hd = 0.17677669529663687f;

    // --- cooperative loads ---
    // qs (scaled): 16x128 = 512 float4
    {
        const float4* gq4 = (const float4*)g_q;
        for (int t = tid; t < TI * 32; t += 256) {
            int r = t >> 5, c4 = t & 31;
            float4 v = gq4[(i0 + r) * 32 + c4];
            v.x *= inv_sqrt_hd; v.y *= inv_sqrt_hd; v.z *= inv_sqrt_hd; v.w *= inv_sqrt_hd;
            *(float4*)&s.qs[r][c4 * 4] = v;
        }
    }
    // ks: 64x128 = 2048 float4
    {
        const float4* gk4 = (const float4*)g_k;
        for (int t = tid; t < TJ * 32; t += 256) {
            int r = t >> 5, c4 = t & 31;
            *(float4*)&s.ks[r][c4 * 4] = gk4[(j0 + r) * 32 + c4];
        }
    }
    // Pib + A4
    for (int t = tid; t < TI * HID; t += 256) {
        int r = t >> 6, m = t & 63;
        s.Pib[r][m] = g_Pib[(i0 + r) * HID + m];
        s.A4[r][m]  = g_A4[(i0 + r) * HID + m];
    }
    // PjT transposed: read coalesced over m, write [m][j]
    for (int t = tid; t < TJ * HID; t += 256) {
        int j = t >> 6, m = t & 63;
        s.PjT[m][j] = g_Pj[(j0 + j) * HID + m];
    }
    if (tid < TI) {
        s.pis[tid][0] = pos[(i0 + tid) * 3 + 0];
        s.pis[tid][1] = pos[(i0 + tid) * 3 + 1];
        s.pis[tid][2] = pos[(i0 + tid) * 3 + 2];
    }
    if (tid < TJ) {
        s.pjs[tid][0] = pos[(j0 + tid) * 3 + 0];
        s.pjs[tid][1] = pos[(j0 + tid) * 3 + 1];
        s.pjs[tid][2] = pos[(j0 + tid) * 3 + 2];
    }
    if (tid < TI * H) {
        s.qb2[tid >> 2][tid & 3] = g_qb2[(i0 + (tid >> 2)) * H + (tid & 3)];
    }
    __syncthreads();

    int il = tid >> 4;          // 0..15
    int jq = (tid & 15) * 4;    // 0,4,...,60

    // acc[h][jj], init with qb2
    float acc[4][4];
#pragma unroll
    for (int h = 0; h < 4; h++) {
        float qb = s.qb2[il][h];
#pragma unroll
        for (int jj = 0; jj < 4; jj++) acc[h][jj] = qb;
    }

    // --- geometry MLP: sum_m relu(Pib_i[m] - Pj_j[m]) * A[i,h,m] ---
#pragma unroll 8
    for (int m = 0; m < HID; m++) {
        float  pib = s.Pib[il][m];
        float4 pj  = *(const float4*)&s.PjT[m][jq];
        float4 a   = s.A4[il][m];
        float h0 = fmaxf(pib - pj.x, 0.f);
        float h1 = fmaxf(pib - pj.y, 0.f);
        float h2 = fmaxf(pib - pj.z, 0.f);
        float h3 = fmaxf(pib - pj.w, 0.f);
        acc[0][0] += h0 * a.x; acc[0][1] += h1 * a.x; acc[0][2] += h2 * a.x; acc[0][3] += h3 * a.x;
        acc[1][0] += h0 * a.y; acc[1][1] += h1 * a.y; acc[1][2] += h2 * a.y; acc[1][3] += h3 * a.y;
        acc[2][0] += h0 * a.z; acc[2][1] += h1 * a.z; acc[2][2] += h2 * a.z; acc[2][3] += h3 * a.z;
        acc[3][0] += h0 * a.w; acc[3][1] += h1 * a.w; acc[3][2] += h2 * a.w; acc[3][3] += h3 * a.w;
    }

    // --- q.k (q already scaled) ---
#pragma unroll
    for (int h = 0; h < 4; h++) {
#pragma unroll
        for (int d = 0; d < HD; d += 4) {
            float4 qv = *(const float4*)&s.qs[il][h * HD + d];
#pragma unroll
            for (int jj = 0; jj < 4; jj++) {
                float4 kv = *(const float4*)&s.ks[jq + jj][h * HD + d];
                acc[h][jj] += qv.x * kv.x + qv.y * kv.y + qv.z * kv.z + qv.w * kv.w;
            }
        }
    }

    // --- dist and store ---
    float pix = s.pis[il][0], piy = s.pis[il][1], piz = s.pis[il][2];
    float dist[4];
#pragma unroll
    for (int jj = 0; jj < 4; jj++) {
        float dx = pix - s.pjs[jq + jj][0];
        float dy = piy - s.pjs[jq + jj][1];
        float dz = piz - s.pjs[jq + jj][2];
        dist[jj] = sqrtf(dx * dx + dy * dy + dz * dz);
    }

    int iglob = i0 + il;
    int jglob = j0 + jq;
#pragma unroll
    for (int h = 0; h < 4; h++) {
        float4 sc;
        sc.x = acc[h][0] - dist[0];
        sc.y = acc[h][1] - dist[1];
        sc.z = acc[h][2] - dist[2];
        sc.w = acc[h][3] - dist[3];
        *(float4*)&g_scores[((size_t)h * N + iglob) * N + jglob] = sc;
    }
}

// ---------------------------------------------------------------
// K4: softmax over j + PV. Block = (head h, 16 rows), 256 threads.
// Phase 1: each warp softmaxes 2 rows. Phase 2: each warp takes a
// 128-wide j slice and accumulates all 16 rows (register blocked),
// then cross-warp reduce through smem.
// ---------------------------------------------------------------
struct SoftmaxSmem {
    float es[16][1028];        // exp(scores - max), padded rows
    float red[8][16][32];      // per-warp partial PV
    float inv_sum[16];
};

__global__ void __launch_bounds__(256) softmax_out_kernel(float* __restrict__ out) {
    extern __shared__ __align__(16) char s_raw[];
    SoftmaxSmem& s = *reinterpret_cast<SoftmaxSmem*>(s_raw);

    int h = blockIdx.y;
    int i0 = blockIdx.x * 16;
    int warp = threadIdx.x >> 5, lane = threadIdx.x & 31;

    // ---- phase 1: softmax (numerator) for rows {warp, warp+8} ----
#pragma unroll
    for (int rr = 0; rr < 2; rr++) {
        int r = warp + rr * 8;
        int i = i0 + r;
        const float4* srow = (const float4*)(g_scores + ((size_t)h * N + i) * N);

        float4 x[8];
        float m = -INFINITY;
#pragma unroll
        for (int t = 0; t < 8; t++) {
            x[t] = srow[t * 32 + lane];
            m = fmaxf(m, fmaxf(fmaxf(x[t].x, x[t].y), fmaxf(x[t].z, x[t].w)));
        }
#pragma unroll
        for (int o = 16; o; o >>= 1) m = fmaxf(m, __shfl_xor_sync(0xFFFFFFFFu, m, o));

        float sum = 0.f;
#pragma unroll
        for (int t = 0; t < 8; t++) {
            float4 e;
            e.x = __expf(x[t].x - m);
            e.y = __expf(x[t].y - m);
            e.z = __expf(x[t].z - m);
            e.w = __expf(x[t].w - m);
            *(float4*)&s.es[r][t * 128 + lane * 4] = e;
            sum += (e.x + e.y) + (e.z + e.w);
        }
#pragma unroll
        for (int o = 16; o; o >>= 1) sum += __shfl_xor_sync(0xFFFFFFFFu, sum, o);
        if (lane == 0) s.inv_sum[r] = 1.0f / sum;
    }
    __syncthreads();

    // ---- phase 2: PV over this warp's j slice, all 16 rows ----
    float acc[16];
#pragma unroll
    for (int r = 0; r < 16; r++) acc[r] = 0.f;

    const float* vb = g_v + h * HD + lane;  // column d = lane
    int jbase = warp * 128;
    for (int j = jbase; j < jbase + 128; j += 4) {
        float v0 = vb[(j + 0) * C];
        float v1 = vb[(j + 1) * C];
        float v2 = vb[(j + 2) * C];
        float v3 = vb[(j + 3) * C];
#pragma unroll
        for (int r = 0; r < 16; r++) {
            float4 e = *(const float4*)&s.es[r][j];
            acc[r] += e.x * v0 + e.y * v1 + e.z * v2 + e.w * v3;
        }
    }
#pragma unroll
    for (int r = 0; r < 16; r++) s.red[warp][r][lane] = acc[r];
    __syncthreads();

    // ---- cross-warp reduce + writeback: 512 outputs, 2 per thread ----
#pragma unroll
    for (int o = threadIdx.x; o < 512; o += 256) {
        int r = o >> 5, d = o & 31;
        float v = 0.f;
#pragma unroll
        for (int w = 0; w < 8; w++) v += s.red[w][r][d];
        out[(i0 + r) * C + h * HD + d] = v * s.inv_sum[r];
    }
}

// ---------------------------------------------------------------
extern "C" void kernel_launch(void* const* d_in, const int* in_sizes, int n_in,
                              void* d_out, int out_size) {
    (void)in_sizes; (void)n_in; (void)out_size;
    const float* x   = (const float*)d_in[0];
    const float* y   = (const float*)d_in[1];
    const float* pos = (const float*)d_in[2];
    const float* Wq  = (const float*)d_in[3];
    const float* bq  = (const float*)d_in[4];
    const float* Wk  = (const float*)d_in[5];
    const float* bk  = (const float*)d_in[6];
    const float* Wv  = (const float*)d_in[7];
    const float* bv  = (const float*)d_in[8];
    const float* W1  = (const float*)d_in[9];
    const float* b1  = (const float*)d_in[10];
    const float* W2  = (const float*)d_in[11];
    const float* b2  = (const float*)d_in[12];
    float* out = (float*)d_out;

    static bool attrs_set = false;
    if (!attrs_set) {
        cudaFuncSetAttribute(scores_kernel, cudaFuncAttributeMaxDynamicSharedMemorySize,
                             (int)sizeof(ScoresSmem));
        cudaFuncSetAttribute(softmax_out_kernel, cudaFuncAttributeMaxDynamicSharedMemorySize,
                             (int)sizeof(SoftmaxSmem));
        attrs_set = true;
    }

    qkv_kernel<<<dim3(N / 16, 3), 128>>>(x, y, Wq, bq, Wk, bk, Wv, bv);
    prep_kernel<<<N, 64>>>(pos, W1, b1, W2, b2);
    scores_kernel<<<dim3(N / TJ, N / TI), 256, sizeof(ScoresSmem)>>>(pos);
    softmax_out_kernel<<<dim3(N / 16, H), 256, sizeof(SoftmaxSmem)>>>(out);
}

// round 4
// speedup vs baseline: 1.4593x; 1.4264x over previous
#include <cuda_runtime.h>
#include <math.h>

#define N 1024
#define C 128
#define H 4
#define HD 32
#define HID 64
#define TI 32
#define TJ 64

// ---- scratch (device globals; no allocation in kernel_launch) ----
__device__ float  g_q[N * C];
__device__ float  g_k[N * C];
__device__ float  g_v[N * C];
__device__ float4 g_A4[N * HID];     // [i][m] -> {A[i,h=0..3,m]}
__device__ float  g_qb2[N * H];      // q[i,h] . b2[h*HD:]
__device__ float  g_Pib[N * HID];    // pos[i]@W1 + b1
__device__ float  g_Pj[N * HID];     // pos[j]@W1
__device__ float  g_scores[(size_t)H * N * N];  // 16MB, L2-resident

// ---------------------------------------------------------------
// K1: q = x@Wq+bq, k = y@Wk+bk, v = y@Wv+bv  (16 rows per block)
// ---------------------------------------------------------------
__global__ void __launch_bounds__(128) qkv_kernel(
        const float* __restrict__ x, const float* __restrict__ y,
        const float* __restrict__ Wq, const float* __restrict__ bq,
        const float* __restrict__ Wk, const float* __restrict__ bk,
        const float* __restrict__ Wv, const float* __restrict__ bv) {
    int n0 = blockIdx.x * 16;
    int which = blockIdx.y;  // 0=q, 1=k, 2=v
    const float* in = (which == 0) ? x : y;
    const float* W  = (which == 0) ? Wq : (which == 1 ? Wk : Wv);
    const float* b  = (which == 0) ? bq : (which == 1 ? bk : bv);
    float* out      = (which == 0) ? g_q : (which == 1 ? g_k : g_v);

    __shared__ float xs[16][C];
    int c = threadIdx.x;
#pragma unroll
    for (int r = 0; r < 16; r++)
        xs[r][c] = in[(n0 + r) * C + c];
    __syncthreads();

    float acc[16];
    float bc = b[c];
#pragma unroll
    for (int r = 0; r < 16; r++) acc[r] = bc;

#pragma unroll 4
    for (int kk = 0; kk < C; kk++) {
        float w = W[kk * C + c];
#pragma unroll
        for (int r = 0; r < 16; r++)
            acc[r] += xs[r][kk] * w;
    }
#pragma unroll
    for (int r = 0; r < 16; r++)
        out[(n0 + r) * C + c] = acc[r];
}

// ---------------------------------------------------------------
// K2: per-row precompute: A4[i][m], qb2[i][h], Pib[i][m], Pj[i][m]
// ---------------------------------------------------------------
__global__ void prep_kernel(const float* __restrict__ pos,
                            const float* __restrict__ W1, const float* __restrict__ b1,
                            const float* __restrict__ W2, const float* __restrict__ b2) {
    int i = blockIdx.x;
    int m = threadIdx.x;  // 0..63

    __shared__ float qs[C];
    qs[m]      = g_q[i * C + m];
    qs[m + 64] = g_q[i * C + m + 64];
    __syncthreads();

    const float* w2row = W2 + m * C;
    float4 a = make_float4(0.f, 0.f, 0.f, 0.f);
#pragma unroll
    for (int d = 0; d < HD; d++) {
        a.x += w2row[0 * HD + d] * qs[0 * HD + d];
        a.y += w2row[1 * HD + d] * qs[1 * HD + d];
        a.z += w2row[2 * HD + d] * qs[2 * HD + d];
        a.w += w2row[3 * HD + d] * qs[3 * HD + d];
    }
    g_A4[i * HID + m] = a;

    float px = pos[i * 3 + 0], py = pos[i * 3 + 1], pz = pos[i * 3 + 2];
    float p1 = px * W1[m] + py * W1[HID + m] + pz * W1[2 * HID + m];
    g_Pj[i * HID + m]  = p1;
    g_Pib[i * HID + m] = p1 + b1[m];

    if (m < H) {
        float s = 0.f;
#pragma unroll
        for (int d = 0; d < HD; d++) s += qs[m * HD + d] * b2[m * HD + d];
        g_qb2[i * H + m] = s;
    }
}

// ---------------------------------------------------------------
// K3: scores. TI=32 x TJ=64, 256 threads. Each thread owns
// 2 i rows (il, il+16) x 4 STRIDED j (jt, jt+16, jt+32, jt+48)
// -> lane-adjacent threads hit adjacent smem rows (no 8-way
// conflicts), kv loads amortized over 2 i.
// ---------------------------------------------------------------
struct ScoresSmem {
    float  qs[TI][132];        // q * inv_sqrt_hd
    float  ks[TJ][132];
    float  Pib[TI][HID + 1];
    float  PjT[HID][TJ + 1];   // transposed: [m][j]
    float4 A4[TI][HID + 2];
    float  pis[TI][3];
    float  pjs[TJ][3];
    float  qb2[TI][4];
};

__global__ void __launch_bounds__(256, 2) scores_kernel(const float* __restrict__ pos) {
    extern __shared__ __align__(16) char s_raw[];
    ScoresSmem& s = *reinterpret_cast<ScoresSmem*>(s_raw);

    int i0 = blockIdx.y * TI;
    int j0 = blockIdx.x * TJ;
    int tid = threadIdx.x;
    const float inv_sqrt_hd = 0.17677669529663687f;

    // --- cooperative loads ---
    {
        const float4* gq4 = (const float4*)g_q;
        for (int t = tid; t < TI * 32; t += 256) {
            int r = t >> 5, c4 = t & 31;
            float4 v = gq4[(i0 + r) * 32 + c4];
            v.x *= inv_sqrt_hd; v.y *= inv_sqrt_hd; v.z *= inv_sqrt_hd; v.w *= inv_sqrt_hd;
            *(float4*)&s.qs[r][c4 * 4] = v;
        }
        const float4* gk4 = (const float4*)g_k;
        for (int t = tid; t < TJ * 32; t += 256) {
            int r = t >> 5, c4 = t & 31;
            *(float4*)&s.ks[r][c4 * 4] = gk4[(j0 + r) * 32 + c4];
        }
    }
    for (int t = tid; t < TI * HID; t += 256) {
        int r = t >> 6, m = t & 63;
        s.Pib[r][m] = g_Pib[(i0 + r) * HID + m];
        s.A4[r][m]  = g_A4[(i0 + r) * HID + m];
    }
    for (int t = tid; t < TJ * HID; t += 256) {
        int j = t >> 6, m = t & 63;
        s.PjT[m][j] = g_Pj[(j0 + j) * HID + m];
    }
    if (tid < TI) {
        s.pis[tid][0] = pos[(i0 + tid) * 3 + 0];
        s.pis[tid][1] = pos[(i0 + tid) * 3 + 1];
        s.pis[tid][2] = pos[(i0 + tid) * 3 + 2];
    }
    if (tid < TJ) {
        s.pjs[tid][0] = pos[(j0 + tid) * 3 + 0];
        s.pjs[tid][1] = pos[(j0 + tid) * 3 + 1];
        s.pjs[tid][2] = pos[(j0 + tid) * 3 + 2];
    }
    if (tid < TI * H) {
        s.qb2[tid >> 2][tid & 3] = g_qb2[(i0 + (tid >> 2)) * H + (tid & 3)];
    }
    __syncthreads();

    int il = tid >> 4;          // 0..15
    int jt = tid & 15;          // j = jt + 16*jj
    int ia = il, ib = il + 16;

    // acc[i][h][jj], init with qb2
    float acc[2][4][4];
#pragma unroll
    for (int h = 0; h < 4; h++) {
        float qa = s.qb2[ia][h], qb = s.qb2[ib][h];
#pragma unroll
        for (int jj = 0; jj < 4; jj++) { acc[0][h][jj] = qa; acc[1][h][jj] = qb; }
    }

    // --- geometry MLP ---
#pragma unroll 4
    for (int m = 0; m < HID; m++) {
        float  pib0 = s.Pib[ia][m];
        float  pib1 = s.Pib[ib][m];
        float4 a0   = s.A4[ia][m];
        float4 a1   = s.A4[ib][m];
        float pj0 = s.PjT[m][jt];
        float pj1 = s.PjT[m][jt + 16];
        float pj2 = s.PjT[m][jt + 32];
        float pj3 = s.PjT[m][jt + 48];

        float h00 = fmaxf(pib0 - pj0, 0.f), h01 = fmaxf(pib0 - pj1, 0.f);
        float h02 = fmaxf(pib0 - pj2, 0.f), h03 = fmaxf(pib0 - pj3, 0.f);
        float h10 = fmaxf(pib1 - pj0, 0.f), h11 = fmaxf(pib1 - pj1, 0.f);
        float h12 = fmaxf(pib1 - pj2, 0.f), h13 = fmaxf(pib1 - pj3, 0.f);

        acc[0][0][0] += h00 * a0.x; acc[0][0][1] += h01 * a0.x; acc[0][0][2] += h02 * a0.x; acc[0][0][3] += h03 * a0.x;
        acc[0][1][0] += h00 * a0.y; acc[0][1][1] += h01 * a0.y; acc[0][1][2] += h02 * a0.y; acc[0][1][3] += h03 * a0.y;
        acc[0][2][0] += h00 * a0.z; acc[0][2][1] += h01 * a0.z; acc[0][2][2] += h02 * a0.z; acc[0][2][3] += h03 * a0.z;
        acc[0][3][0] += h00 * a0.w; acc[0][3][1] += h01 * a0.w; acc[0][3][2] += h02 * a0.w; acc[0][3][3] += h03 * a0.w;
        acc[1][0][0] += h10 * a1.x; acc[1][0][1] += h11 * a1.x; acc[1][0][2] += h12 * a1.x; acc[1][0][3] += h13 * a1.x;
        acc[1][1][0] += h10 * a1.y; acc[1][1][1] += h11 * a1.y; acc[1][1][2] += h12 * a1.y; acc[1][1][3] += h13 * a1.y;
        acc[1][2][0] += h10 * a1.z; acc[1][2][1] += h11 * a1.z; acc[1][2][2] += h12 * a1.z; acc[1][2][3] += h13 * a1.z;
        acc[1][3][0] += h10 * a1.w; acc[1][3][1] += h11 * a1.w; acc[1][3][2] += h12 * a1.w; acc[1][3][3] += h13 * a1.w;
    }

    // --- q.k (q pre-scaled) ---
#pragma unroll
    for (int h = 0; h < 4; h++) {
#pragma unroll
        for (int d = 0; d < HD; d += 4) {
            float4 q0 = *(const float4*)&s.qs[ia][h * HD + d];
            float4 q1 = *(const float4*)&s.qs[ib][h * HD + d];
#pragma unroll
            for (int jj = 0; jj < 4; jj++) {
                float4 kv = *(const float4*)&s.ks[jj * 16 + jt][h * HD + d];
                acc[0][h][jj] += q0.x * kv.x + q0.y * kv.y + q0.z * kv.z + q0.w * kv.w;
                acc[1][h][jj] += q1.x * kv.x + q1.y * kv.y + q1.z * kv.z + q1.w * kv.w;
            }
        }
    }

    // --- dist + store ---
    float dist0[4], dist1[4];
    float pax = s.pis[ia][0], pay = s.pis[ia][1], paz = s.pis[ia][2];
    float pbx = s.pis[ib][0], pby = s.pis[ib][1], pbz = s.pis[ib][2];
#pragma unroll
    for (int jj = 0; jj < 4; jj++) {
        int j = jj * 16 + jt;
        float jx = s.pjs[j][0], jy = s.pjs[j][1], jz = s.pjs[j][2];
        float dax = pax - jx, day = pay - jy, daz = paz - jz;
        float dbx = pbx - jx, dby = pby - jy, dbz = pbz - jz;
        dist0[jj] = sqrtf(dax * dax + day * day + daz * daz);
        dist1[jj] = sqrtf(dbx * dbx + dby * dby + dbz * dbz);
    }

#pragma unroll
    for (int h = 0; h < 4; h++) {
        size_t basea = ((size_t)h * N + (i0 + ia)) * N + j0;
        size_t baseb = ((size_t)h * N + (i0 + ib)) * N + j0;
#pragma unroll
        for (int jj = 0; jj < 4; jj++) {
            g_scores[basea + jj * 16 + jt] = acc[0][h][jj] - dist0[jj];
            g_scores[baseb + jj * 16 + jt] = acc[1][h][jj] - dist1[jj];
        }
    }
}

// ---------------------------------------------------------------
// K4: softmax over j + PV. Block = (head h, 16 rows), 256 threads.
// ---------------------------------------------------------------
struct SoftmaxSmem {
    float es[16][1028];        // exp(scores - max), padded rows
    float red[8][16][32];      // per-warp partial PV
    float inv_sum[16];
};

__global__ void __launch_bounds__(256) softmax_out_kernel(float* __restrict__ out) {
    extern __shared__ __align__(16) char s_raw[];
    SoftmaxSmem& s = *reinterpret_cast<SoftmaxSmem*>(s_raw);

    int h = blockIdx.y;
    int i0 = blockIdx.x * 16;
    int warp = threadIdx.x >> 5, lane = threadIdx.x & 31;

    // ---- phase 1: softmax numerator for rows {warp, warp+8} ----
#pragma unroll
    for (int rr = 0; rr < 2; rr++) {
        int r = warp + rr * 8;
        int i = i0 + r;
        const float4* srow = (const float4*)(g_scores + ((size_t)h * N + i) * N);

        float4 x[8];
        float m = -INFINITY;
#pragma unroll
        for (int t = 0; t < 8; t++) {
            x[t] = srow[t * 32 + lane];
            m = fmaxf(m, fmaxf(fmaxf(x[t].x, x[t].y), fmaxf(x[t].z, x[t].w)));
        }
#pragma unroll
        for (int o = 16; o; o >>= 1) m = fmaxf(m, __shfl_xor_sync(0xFFFFFFFFu, m, o));

        float sum = 0.f;
#pragma unroll
        for (int t = 0; t < 8; t++) {
            float4 e;
            e.x = __expf(x[t].x - m);
            e.y = __expf(x[t].y - m);
            e.z = __expf(x[t].z - m);
            e.w = __expf(x[t].w - m);
            *(float4*)&s.es[r][t * 128 + lane * 4] = e;
            sum += (e.x + e.y) + (e.z + e.w);
        }
#pragma unroll
        for (int o = 16; o; o >>= 1) sum += __shfl_xor_sync(0xFFFFFFFFu, sum, o);
        if (lane == 0) s.inv_sum[r] = 1.0f / sum;
    }
    __syncthreads();

    // ---- phase 2: PV over this warp's 128-wide j slice, 16 rows ----
    float acc[16];
#pragma unroll
    for (int r = 0; r < 16; r++) acc[r] = 0.f;

    const float* vb = g_v + h * HD + lane;  // column d = lane
    int jbase = warp * 128;
    for (int j = jbase; j < jbase + 128; j += 8) {
        float v0 = vb[(j + 0) * C];
        float v1 = vb[(j + 1) * C];
        float v2 = vb[(j + 2) * C];
        float v3 = vb[(j + 3) * C];
        float v4 = vb[(j + 4) * C];
        float v5 = vb[(j + 5) * C];
        float v6 = vb[(j + 6) * C];
        float v7 = vb[(j + 7) * C];
#pragma unroll
        for (int r = 0; r < 16; r++) {
            float4 e0 = *(const float4*)&s.es[r][j];
            float4 e1 = *(const float4*)&s.es[r][j + 4];
            acc[r] += e0.x * v0 + e0.y * v1 + e0.z * v2 + e0.w * v3
                    + e1.x * v4 + e1.y * v5 + e1.z * v6 + e1.w * v7;
        }
    }
#pragma unroll
    for (int r = 0; r < 16; r++) s.red[warp][r][lane] = acc[r];
    __syncthreads();

    // ---- cross-warp reduce + writeback ----
#pragma unroll
    for (int o = threadIdx.x; o < 512; o += 256) {
        int r = o >> 5, d = o & 31;
        float v = 0.f;
#pragma unroll
        for (int w = 0; w < 8; w++) v += s.red[w][r][d];
        out[(i0 + r) * C + h * HD + d] = v * s.inv_sum[r];
    }
}

// ---------------------------------------------------------------
extern "C" void kernel_launch(void* const* d_in, const int* in_sizes, int n_in,
                              void* d_out, int out_size) {
    (void)in_sizes; (void)n_in; (void)out_size;
    const float* x   = (const float*)d_in[0];
    const float* y   = (const float*)d_in[1];
    const float* pos = (const float*)d_in[2];
    const float* Wq  = (const float*)d_in[3];
    const float* bq  = (const float*)d_in[4];
    const float* Wk  = (const float*)d_in[5];
    const float* bk  = (const float*)d_in[6];
    const float* Wv  = (const float*)d_in[7];
    const float* bv  = (const float*)d_in[8];
    const float* W1  = (const float*)d_in[9];
    const float* b1  = (const float*)d_in[10];
    const float* W2  = (const float*)d_in[11];
    const float* b2  = (const float*)d_in[12];
    float* out = (float*)d_out;

    static bool attrs_set = false;
    if (!attrs_set) {
        cudaFuncSetAttribute(scores_kernel, cudaFuncAttributeMaxDynamicSharedMemorySize,
                             (int)sizeof(ScoresSmem));
        cudaFuncSetAttribute(softmax_out_kernel, cudaFuncAttributeMaxDynamicSharedMemorySize,
                             (int)sizeof(SoftmaxSmem));
        attrs_set = true;
    }

    qkv_kernel<<<dim3(N / 16, 3), 128>>>(x, y, Wq, bq, Wk, bk, Wv, bv);
    prep_kernel<<<N, 64>>>(pos, W1, b1, W2, b2);
    scores_kernel<<<dim3(N / TJ, N / TI), 256, sizeof(ScoresSmem)>>>(pos);
    softmax_out_kernel<<<dim3(N / 16, H), 256, sizeof(SoftmaxSmem)>>>(out);
}

// round 5
// speedup vs baseline: 2.0873x; 1.4303x over previous
#include <cuda_runtime.h>
#include <math.h>

#define N 1024
#define C 128
#define H 4
#define HD 32
#define HID 64
#define TI 32
#define TJ 64

typedef unsigned long long u64;

// ---- packed f32x2 helpers (sm_103a) ----
#define PACK2(d, lo, hi) asm("mov.b64 %0, {%1, %2};" : "=l"(d) : "f"(lo), "f"(hi))
#define UNPACK2(lo, hi, s) asm("mov.b64 {%0, %1}, %2;" : "=f"(lo), "=f"(hi) : "l"(s))
#define ADD2(d, a, b) asm("add.rn.f32x2 %0, %1, %2;" : "=l"(d) : "l"(a), "l"(b))
#define FMA2(d, a, b) asm("fma.rn.f32x2 %0, %1, %2, %0;" : "+l"(d) : "l"(a), "l"(b))

// ---- scratch (device globals) ----
__device__ float  g_q[N * C];
__device__ float  g_k[N * C];
__device__ float  g_v[N * C];
__device__ float4 g_A4[N * HID];     // [i][m] -> {A[i,h=0..3,m]}
__device__ float  g_qb2[N * H];
__device__ float  g_Pib[N * HID];    // pos[i]@W1 + b1
__device__ float  g_negPj[N * HID];  // -(pos[j]@W1)
__device__ float  g_scores[(size_t)H * N * N];

// ---------------------------------------------------------------
// K1: q = x@Wq+bq, k = y@Wk+bk, v = y@Wv+bv  (16 rows per block)
// ---------------------------------------------------------------
__global__ void __launch_bounds__(128) qkv_kernel(
        const float* __restrict__ x, const float* __restrict__ y,
        const float* __restrict__ Wq, const float* __restrict__ bq,
        const float* __restrict__ Wk, const float* __restrict__ bk,
        const float* __restrict__ Wv, const float* __restrict__ bv) {
    int n0 = blockIdx.x * 16;
    int which = blockIdx.y;
    const float* in = (which == 0) ? x : y;
    const float* W  = (which == 0) ? Wq : (which == 1 ? Wk : Wv);
    const float* b  = (which == 0) ? bq : (which == 1 ? bk : bv);
    float* out      = (which == 0) ? g_q : (which == 1 ? g_k : g_v);

    __shared__ float xs[16][C];
    int c = threadIdx.x;
#pragma unroll
    for (int r = 0; r < 16; r++)
        xs[r][c] = in[(n0 + r) * C + c];
    __syncthreads();

    float acc[16];
    float bc = b[c];
#pragma unroll
    for (int r = 0; r < 16; r++) acc[r] = bc;

#pragma unroll 4
    for (int kk = 0; kk < C; kk++) {
        float w = W[kk * C + c];
#pragma unroll
        for (int r = 0; r < 16; r++)
            acc[r] += xs[r][kk] * w;
    }
#pragma unroll
    for (int r = 0; r < 16; r++)
        out[(n0 + r) * C + c] = acc[r];
}

// ---------------------------------------------------------------
// K2 v2: coalesced prep. 64 blocks x 256 threads; each block does
// 16 i-rows; W2 staged in smem (read coalesced ONCE per block).
// ---------------------------------------------------------------
__global__ void __launch_bounds__(256) prep_kernel(
        const float* __restrict__ pos,
        const float* __restrict__ W1, const float* __restrict__ b1,
        const float* __restrict__ W2, const float* __restrict__ b2) {
    int i0 = blockIdx.x * 16;
    __shared__ float W2s[HID][C + 1];
    __shared__ float qs[16][C];
    __shared__ float b2s[C];

    int t = threadIdx.x;
    for (int idx = t; idx < HID * C; idx += 256)
        W2s[idx >> 7][idx & 127] = W2[idx];
    for (int idx = t; idx < 16 * C; idx += 256)
        qs[idx >> 7][idx & 127] = g_q[(i0 + (idx >> 7)) * C + (idx & 127)];
    if (t < C) b2s[t] = b2[t];
    __syncthreads();

    int m = t & 63;
    int isub = t >> 6;
    float w1x = W1[m], w1y = W1[HID + m], w1z = W1[2 * HID + m];
    float b1m = b1[m];

#pragma unroll
    for (int p = 0; p < 4; p++) {
        int il = p * 4 + isub;
        int i = i0 + il;
        const float* qrow = qs[il];

        float4 a = make_float4(0.f, 0.f, 0.f, 0.f);
#pragma unroll
        for (int d = 0; d < HD; d++) {
            a.x += W2s[m][0 * HD + d] * qrow[0 * HD + d];
            a.y += W2s[m][1 * HD + d] * qrow[1 * HD + d];
            a.z += W2s[m][2 * HD + d] * qrow[2 * HD + d];
            a.w += W2s[m][3 * HD + d] * qrow[3 * HD + d];
        }
        g_A4[i * HID + m] = a;

        float px = pos[i * 3 + 0], py = pos[i * 3 + 1], pz = pos[i * 3 + 2];
        float p1 = px * w1x + py * w1y + pz * w1z;
        g_negPj[i * HID + m] = -p1;
        g_Pib[i * HID + m]   = p1 + b1m;

        if (m < H) {
            float s = 0.f;
#pragma unroll
            for (int d = 0; d < HD; d++) s += qrow[m * HD + d] * b2s[m * HD + d];
            g_qb2[i * H + m] = s;
        }
    }
}

// ---------------------------------------------------------------
// K3: scores, packed f32x2. TI=32 x TJ=64, 256 threads.
// Thread (il, jt): i in {il, il+16}; j pairs {2jt,2jt+1},{2jt+32,2jt+33}.
// acc[i][h][pair] is a packed f32x2 over the adjacent-j pair.
// ---------------------------------------------------------------
struct ScoresSmem {
    float  qs[TI][132];        // q * inv_sqrt_hd (row 528B: 8B-aligned at even c)
    float  ksT[C][TJ + 2];     // transposed k: [c][j], rows 264B (8B-aligned)
    float  Pib[TI][HID];
    float  nPjT[HID][TJ + 2];  // transposed -Pj: [m][j]
    float4 A4[TI][HID + 2];
    float  pis[TI][3];
    float  pjs[TJ][3];
    float  qb2[TI][4];
};

__global__ void __launch_bounds__(256, 2) scores_kernel(const float* __restrict__ pos) {
    extern __shared__ __align__(16) char s_raw[];
    ScoresSmem& s = *reinterpret_cast<ScoresSmem*>(s_raw);

    int i0 = blockIdx.y * TI;
    int j0 = blockIdx.x * TJ;
    int tid = threadIdx.x;
    const float inv_sqrt_hd = 0.17677669529663687f;

    // --- cooperative loads ---
    {
        const float4* gq4 = (const float4*)g_q;
        for (int t = tid; t < TI * 32; t += 256) {
            int r = t >> 5, c4 = t & 31;
            float4 v = gq4[(i0 + r) * 32 + c4];
            v.x *= inv_sqrt_hd; v.y *= inv_sqrt_hd; v.z *= inv_sqrt_hd; v.w *= inv_sqrt_hd;
            *(float4*)&s.qs[r][c4 * 4] = v;
        }
        // k: register-staged transpose -> ksT[c][j]
        const float4* gk4 = (const float4*)g_k;
        for (int t = tid; t < TJ * 32; t += 256) {
            int j = t >> 5, c4 = t & 31;
            float4 v = gk4[(j0 + j) * 32 + c4];
            s.ksT[c4 * 4 + 0][j] = v.x;
            s.ksT[c4 * 4 + 1][j] = v.y;
            s.ksT[c4 * 4 + 2][j] = v.z;
            s.ksT[c4 * 4 + 3][j] = v.w;
        }
        // -Pj: register-staged transpose -> nPjT[m][j]
        const float4* gp4 = (const float4*)g_negPj;
        for (int t = tid; t < TJ * 16; t += 256) {
            int j = t >> 4, m4 = t & 15;
            float4 v = gp4[(j0 + j) * 16 + m4];
            s.nPjT[m4 * 4 + 0][j] = v.x;
            s.nPjT[m4 * 4 + 1][j] = v.y;
            s.nPjT[m4 * 4 + 2][j] = v.z;
            s.nPjT[m4 * 4 + 3][j] = v.w;
        }
    }
    for (int t = tid; t < TI * HID; t += 256) {
        int r = t >> 6, m = t & 63;
        s.Pib[r][m] = g_Pib[(i0 + r) * HID + m];
        s.A4[r][m]  = g_A4[(i0 + r) * HID + m];
    }
    if (tid < TI) {
        s.pis[tid][0] = pos[(i0 + tid) * 3 + 0];
        s.pis[tid][1] = pos[(i0 + tid) * 3 + 1];
        s.pis[tid][2] = pos[(i0 + tid) * 3 + 2];
    }
    if (tid < TJ) {
        s.pjs[tid][0] = pos[(j0 + tid) * 3 + 0];
        s.pjs[tid][1] = pos[(j0 + tid) * 3 + 1];
        s.pjs[tid][2] = pos[(j0 + tid) * 3 + 2];
    }
    if (tid < TI * H) {
        s.qb2[tid >> 2][tid & 3] = g_qb2[(i0 + (tid >> 2)) * H + (tid & 3)];
    }
    __syncthreads();

    int il = tid >> 4;          // 0..15
    int jt = tid & 15;
    int ia = il, ib = il + 16;
    int jc0 = 2 * jt;           // pair 0 cols {jc0, jc0+1}
    int jc1 = 2 * jt + 32;      // pair 1 cols

    // acc[i][h][pair] packed over adjacent-j pair; init with qb2 dup
    u64 acc[2][4][2];
#pragma unroll
    for (int h = 0; h < 4; h++) {
        float qa = s.qb2[ia][h], qb = s.qb2[ib][h];
        u64 ta, tb;
        PACK2(ta, qa, qa); PACK2(tb, qb, qb);
        acc[0][h][0] = ta; acc[0][h][1] = ta;
        acc[1][h][0] = tb; acc[1][h][1] = tb;
    }

    // --- geometry MLP, packed ---
#pragma unroll 4
    for (int m = 0; m < HID; m++) {
        float pa = s.Pib[ia][m], pb = s.Pib[ib][m];
        u64 pa2, pb2;
        PACK2(pa2, pa, pa); PACK2(pb2, pb, pb);
        u64 n0 = *(const u64*)&s.nPjT[m][jc0];
        u64 n1 = *(const u64*)&s.nPjT[m][jc1];

        u64 za0, za1, zb0, zb1;
        ADD2(za0, pa2, n0); ADD2(za1, pa2, n1);
        ADD2(zb0, pb2, n0); ADD2(zb1, pb2, n1);

        float lo, hi;
        u64 ha0, ha1, hb0, hb1;
        UNPACK2(lo, hi, za0); PACK2(ha0, fmaxf(lo, 0.f), fmaxf(hi, 0.f));
        UNPACK2(lo, hi, za1); PACK2(ha1, fmaxf(lo, 0.f), fmaxf(hi, 0.f));
        UNPACK2(lo, hi, zb0); PACK2(hb0, fmaxf(lo, 0.f), fmaxf(hi, 0.f));
        UNPACK2(lo, hi, zb1); PACK2(hb1, fmaxf(lo, 0.f), fmaxf(hi, 0.f));

        float4 aa = s.A4[ia][m], ab = s.A4[ib][m];
        u64 ax, ay, az, aw, bx, by, bz, bw;
        PACK2(ax, aa.x, aa.x); PACK2(ay, aa.y, aa.y);
        PACK2(az, aa.z, aa.z); PACK2(aw, aa.w, aa.w);
        PACK2(bx, ab.x, ab.x); PACK2(by, ab.y, ab.y);
        PACK2(bz, ab.z, ab.z); PACK2(bw, ab.w, ab.w);

        FMA2(acc[0][0][0], ha0, ax); FMA2(acc[0][0][1], ha1, ax);
        FMA2(acc[0][1][0], ha0, ay); FMA2(acc[0][1][1], ha1, ay);
        FMA2(acc[0][2][0], ha0, az); FMA2(acc[0][2][1], ha1, az);
        FMA2(acc[0][3][0], ha0, aw); FMA2(acc[0][3][1], ha1, aw);
        FMA2(acc[1][0][0], hb0, bx); FMA2(acc[1][0][1], hb1, bx);
        FMA2(acc[1][1][0], hb0, by); FMA2(acc[1][1][1], hb1, by);
        FMA2(acc[1][2][0], hb0, bz); FMA2(acc[1][2][1], hb1, bz);
        FMA2(acc[1][3][0], hb0, bw); FMA2(acc[1][3][1], hb1, bw);
    }

    // --- q.k, packed over j pairs (k transposed; q pre-scaled) ---
#pragma unroll
    for (int h = 0; h < 4; h++) {
#pragma unroll
        for (int d2 = 0; d2 < 16; d2++) {
            int c = h * HD + 2 * d2;
            float2 qa = *(const float2*)&s.qs[ia][c];
            float2 qb = *(const float2*)&s.qs[ib][c];
            u64 k00 = *(const u64*)&s.ksT[c][jc0];
            u64 k01 = *(const u64*)&s.ksT[c][jc1];
            u64 k10 = *(const u64*)&s.ksT[c + 1][jc0];
            u64 k11 = *(const u64*)&s.ksT[c + 1][jc1];
            u64 qa0, qa1, qb0, qb1;
            PACK2(qa0, qa.x, qa.x); PACK2(qa1, qa.y, qa.y);
            PACK2(qb0, qb.x, qb.x); PACK2(qb1, qb.y, qb.y);
            FMA2(acc[0][h][0], qa0, k00); FMA2(acc[0][h][1], qa0, k01);
            FMA2(acc[0][h][0], qa1, k10); FMA2(acc[0][h][1], qa1, k11);
            FMA2(acc[1][h][0], qb0, k00); FMA2(acc[1][h][1], qb0, k01);
            FMA2(acc[1][h][0], qb1, k10); FMA2(acc[1][h][1], qb1, k11);
        }
    }

    // --- dist (per i, per pair, 2 j each) ---
    float pax = s.pis[ia][0], pay = s.pis[ia][1], paz = s.pis[ia][2];
    float pbx = s.pis[ib][0], pby = s.pis[ib][1], pbz = s.pis[ib][2];
    float da[2][2], db[2][2];
#pragma unroll
    for (int p = 0; p < 2; p++) {
        int jc = (p == 0) ? jc0 : jc1;
#pragma unroll
        for (int e = 0; e < 2; e++) {
            int j = jc + e;
            float jx = s.pjs[j][0], jy = s.pjs[j][1], jz = s.pjs[j][2];
            float x0 = pax - jx, y0_ = pay - jy, z0 = paz - jz;
            float x1 = pbx - jx, y1_ = pby - jy, z1 = pbz - jz;
            da[p][e] = sqrtf(x0 * x0 + y0_ * y0_ + z0 * z0);
            db[p][e] = sqrtf(x1 * x1 + y1_ * y1_ + z1 * z1);
        }
    }

    // --- store: coalesced float2 ---
    int iga = i0 + ia, igb = i0 + ib;
#pragma unroll
    for (int h = 0; h < 4; h++) {
        size_t basea = ((size_t)h * N + iga) * N + j0;
        size_t baseb = ((size_t)h * N + igb) * N + j0;
#pragma unroll
        for (int p = 0; p < 2; p++) {
            int jc = (p == 0) ? jc0 : jc1;
            float lo, hi;
            UNPACK2(lo, hi, acc[0][h][p]);
            float2 sca = make_float2(lo - da[p][0], hi - da[p][1]);
            UNPACK2(lo, hi, acc[1][h][p]);
            float2 scb = make_float2(lo - db[p][0], hi - db[p][1]);
            *(float2*)&g_scores[basea + jc] = sca;
            *(float2*)&g_scores[baseb + jc] = scb;
        }
    }
}

// ---------------------------------------------------------------
// K4: softmax over j + PV (unchanged from R4)
// ---------------------------------------------------------------
struct SoftmaxSmem {
    float es[16][1028];
    float red[8][16][32];
    float inv_sum[16];
};

__global__ void __launch_bounds__(256) softmax_out_kernel(float* __restrict__ out) {
    extern __shared__ __align__(16) char s_raw[];
    SoftmaxSmem& s = *reinterpret_cast<SoftmaxSmem*>(s_raw);

    int h = blockIdx.y;
    int i0 = blockIdx.x * 16;
    int warp = threadIdx.x >> 5, lane = threadIdx.x & 31;

#pragma unroll
    for (int rr = 0; rr < 2; rr++) {
        int r = warp + rr * 8;
        int i = i0 + r;
        const float4* srow = (const float4*)(g_scores + ((size_t)h * N + i) * N);

        float4 x[8];
        float m = -INFINITY;
#pragma unroll
        for (int t = 0; t < 8; t++) {
            x[t] = srow[t * 32 + lane];
            m = fmaxf(m, fmaxf(fmaxf(x[t].x, x[t].y), fmaxf(x[t].z, x[t].w)));
        }
#pragma unroll
        for (int o = 16; o; o >>= 1) m = fmaxf(m, __shfl_xor_sync(0xFFFFFFFFu, m, o));

        float sum = 0.f;
#pragma unroll
        for (int t = 0; t < 8; t++) {
            float4 e;
            e.x = __expf(x[t].x - m);
            e.y = __expf(x[t].y - m);
            e.z = __expf(x[t].z - m);
            e.w = __expf(x[t].w - m);
            *(float4*)&s.es[r][t * 128 + lane * 4] = e;
            sum += (e.x + e.y) + (e.z + e.w);
        }
#pragma unroll
        for (int o = 16; o; o >>= 1) sum += __shfl_xor_sync(0xFFFFFFFFu, sum, o);
        if (lane == 0) s.inv_sum[r] = 1.0f / sum;
    }
    __syncthreads();

    float acc[16];
#pragma unroll
    for (int r = 0; r < 16; r++) acc[r] = 0.f;

    const float* vb = g_v + h * HD + lane;
    int jbase = warp * 128;
    for (int j = jbase; j < jbase + 128; j += 8) {
        float v0 = vb[(j + 0) * C];
        float v1 = vb[(j + 1) * C];
        float v2 = vb[(j + 2) * C];
        float v3 = vb[(j + 3) * C];
        float v4 = vb[(j + 4) * C];
        float v5 = vb[(j + 5) * C];
        float v6 = vb[(j + 6) * C];
        float v7 = vb[(j + 7) * C];
#pragma unroll
        for (int r = 0; r < 16; r++) {
            float4 e0 = *(const float4*)&s.es[r][j];
            float4 e1 = *(const float4*)&s.es[r][j + 4];
            acc[r] += e0.x * v0 + e0.y * v1 + e0.z * v2 + e0.w * v3
                    + e1.x * v4 + e1.y * v5 + e1.z * v6 + e1.w * v7;
        }
    }
#pragma unroll
    for (int r = 0; r < 16; r++) s.red[warp][r][lane] = acc[r];
    __syncthreads();

#pragma unroll
    for (int o = threadIdx.x; o < 512; o += 256) {
        int r = o >> 5, d = o & 31;
        float v = 0.f;
#pragma unroll
        for (int w = 0; w < 8; w++) v += s.red[w][r][d];
        out[(i0 + r) * C + h * HD + d] = v * s.inv_sum[r];
    }
}

// ---------------------------------------------------------------
extern "C" void kernel_launch(void* const* d_in, const int* in_sizes, int n_in,
                              void* d_out, int out_size) {
    (void)in_sizes; (void)n_in; (void)out_size;
    const float* x   = (const float*)d_in[0];
    const float* y   = (const float*)d_in[1];
    const float* pos = (const float*)d_in[2];
    const float* Wq  = (const float*)d_in[3];
    const float* bq  = (const float*)d_in[4];
    const float* Wk  = (const float*)d_in[5];
    const float* bk  = (const float*)d_in[6];
    const float* Wv  = (const float*)d_in[7];
    const float* bv  = (const float*)d_in[8];
    const float* W1  = (const float*)d_in[9];
    const float* b1  = (const float*)d_in[10];
    const float* W2  = (const float*)d_in[11];
    const float* b2  = (const float*)d_in[12];
    float* out = (float*)d_out;

    static bool attrs_set = false;
    if (!attrs_set) {
        cudaFuncSetAttribute(scores_kernel, cudaFuncAttributeMaxDynamicSharedMemorySize,
                             (int)sizeof(ScoresSmem));
        cudaFuncSetAttribute(softmax_out_kernel, cudaFuncAttributeMaxDynamicSharedMemorySize,
                             (int)sizeof(SoftmaxSmem));
        attrs_set = true;
    }

    qkv_kernel<<<dim3(N / 16, 3), 128>>>(x, y, Wq, bq, Wk, bk, Wv, bv);
    prep_kernel<<<N / 16, 256>>>(pos, W1, b1, W2, b2);
    scores_kernel<<<dim3(N / TJ, N / TI), 256, sizeof(ScoresSmem)>>>(pos);
    softmax_out_kernel<<<dim3(N / 16, H), 256, sizeof(SoftmaxSmem)>>>(out);
}

// round 6
// speedup vs baseline: 2.1718x; 1.0405x over previous
#include <cuda_runtime.h>
#include <math.h>

#define N 1024
#define C 128
#define H 4
#define HD 32
#define HID 64
#define TI 32
#define TJ 64

typedef unsigned long long u64;

// ---- packed f32x2 helpers (sm_103a) ----
#define PACK2(d, lo, hi) asm("mov.b64 %0, {%1, %2};" : "=l"(d) : "f"(lo), "f"(hi))
#define UNPACK2(lo, hi, s) asm("mov.b64 {%0, %1}, %2;" : "=f"(lo), "=f"(hi) : "l"(s))
#define ADD2(d, a, b) asm("add.rn.f32x2 %0, %1, %2;" : "=l"(d) : "l"(a), "l"(b))
#define FMA2(d, a, b) asm("fma.rn.f32x2 %0, %1, %2, %0;" : "+l"(d) : "l"(a), "l"(b))

// ---- scratch (device globals) ----
__device__ float  g_q[N * C];
__device__ float  g_k[N * C];
__device__ float  g_v[N * C];
__device__ float4 g_A4[N * HID];     // [i][m] -> {A[i,h=0..3,m]}
__device__ float  g_qb2[N * H];
__device__ float  g_Pib[N * HID];    // pos[i]@W1 + b1
__device__ float  g_negPj[N * HID];  // -(pos[j]@W1)
__device__ float  g_scores[(size_t)H * N * N];

// ---------------------------------------------------------------
// K1: qkv + (for q-blocks) fused prep. grid (N/16, 3), block 128.
// ---------------------------------------------------------------
__global__ void __launch_bounds__(128) qkv_prep_kernel(
        const float* __restrict__ x, const float* __restrict__ y,
        const float* __restrict__ pos,
        const float* __restrict__ Wq, const float* __restrict__ bq,
        const float* __restrict__ Wk, const float* __restrict__ bk,
        const float* __restrict__ Wv, const float* __restrict__ bv,
        const float* __restrict__ W1, const float* __restrict__ b1,
        const float* __restrict__ W2, const float* __restrict__ b2) {
    int n0 = blockIdx.x * 16;
    int which = blockIdx.y;  // 0=q(+prep), 1=k, 2=v
    const float* in = (which == 0) ? x : y;
    const float* W  = (which == 0) ? Wq : (which == 1 ? Wk : Wv);
    const float* b  = (which == 0) ? bq : (which == 1 ? bk : bv);
    float* out      = (which == 0) ? g_q : (which == 1 ? g_k : g_v);

    __shared__ float xs[16][C];          // x rows, later reused for q rows
    __shared__ float W2s[HID][C + 4];
    __shared__ float b2s[C];

    int c = threadIdx.x;
#pragma unroll
    for (int r = 0; r < 16; r++)
        xs[r][c] = in[(n0 + r) * C + c];
    __syncthreads();

    float acc[16];
    float bc = b[c];
#pragma unroll
    for (int r = 0; r < 16; r++) acc[r] = bc;

#pragma unroll 4
    for (int kk = 0; kk < C; kk++) {
        float w = W[kk * C + c];
#pragma unroll
        for (int r = 0; r < 16; r++)
            acc[r] += xs[r][kk] * w;
    }
#pragma unroll
    for (int r = 0; r < 16; r++)
        out[(n0 + r) * C + c] = acc[r];

    if (which != 0) return;

    // ---- fused prep: q rows live in acc[] ----
    __syncthreads();                     // everyone done reading xs
#pragma unroll
    for (int r = 0; r < 16; r++) xs[r][c] = acc[r];   // xs := q rows
    for (int idx = c; idx < HID * C; idx += 128)
        W2s[idx >> 7][idx & 127] = W2[idx];
    b2s[c] = b2[c];
    __syncthreads();

    int m = c & 63;
    int half = c >> 6;  // rows half*8 .. half*8+7
    float w1x = W1[m], w1y = W1[HID + m], w1z = W1[2 * HID + m];
    float b1m = b1[m];

#pragma unroll
    for (int p = 0; p < 8; p++) {
        int il = half * 8 + p;
        int i = n0 + il;
        const float* qrow = xs[il];

        float4 a = make_float4(0.f, 0.f, 0.f, 0.f);
#pragma unroll
        for (int d = 0; d < HD; d++) {
            a.x += W2s[m][0 * HD + d] * qrow[0 * HD + d];
            a.y += W2s[m][1 * HD + d] * qrow[1 * HD + d];
            a.z += W2s[m][2 * HD + d] * qrow[2 * HD + d];
            a.w += W2s[m][3 * HD + d] * qrow[3 * HD + d];
        }
        g_A4[i * HID + m] = a;

        float px = pos[i * 3 + 0], py = pos[i * 3 + 1], pz = pos[i * 3 + 2];
        float p1 = px * w1x + py * w1y + pz * w1z;
        g_negPj[i * HID + m] = -p1;
        g_Pib[i * HID + m]   = p1 + b1m;

        if (m < H) {
            float s = 0.f;
#pragma unroll
            for (int d = 0; d < HD; d++) s += qrow[m * HD + d] * b2s[m * HD + d];
            g_qb2[i * H + m] = s;
        }
    }
}

// ---------------------------------------------------------------
// K3: scores, packed f32x2 (unchanged structure from R5).
// ---------------------------------------------------------------
struct ScoresSmem {
    float  qs[TI][132];
    float  ksT[C][TJ + 2];
    float  Pib[TI][HID];
    float  nPjT[HID][TJ + 2];
    float4 A4[TI][HID + 2];
    float  pis[TI][3];
    float  pjs[TJ][3];
    float  qb2[TI][4];
};

__global__ void __launch_bounds__(256, 2) scores_kernel(const float* __restrict__ pos) {
    extern __shared__ __align__(16) char s_raw[];
    ScoresSmem& s = *reinterpret_cast<ScoresSmem*>(s_raw);

    int i0 = blockIdx.y * TI;
    int j0 = blockIdx.x * TJ;
    int tid = threadIdx.x;
    const float inv_sqrt_hd = 0.17677669529663687f;

    {
        const float4* gq4 = (const float4*)g_q;
        for (int t = tid; t < TI * 32; t += 256) {
            int r = t >> 5, c4 = t & 31;
            float4 v = gq4[(i0 + r) * 32 + c4];
            v.x *= inv_sqrt_hd; v.y *= inv_sqrt_hd; v.z *= inv_sqrt_hd; v.w *= inv_sqrt_hd;
            *(float4*)&s.qs[r][c4 * 4] = v;
        }
        const float4* gk4 = (const float4*)g_k;
        for (int t = tid; t < TJ * 32; t += 256) {
            int j = t >> 5, c4 = t & 31;
            float4 v = gk4[(j0 + j) * 32 + c4];
            s.ksT[c4 * 4 + 0][j] = v.x;
            s.ksT[c4 * 4 + 1][j] = v.y;
            s.ksT[c4 * 4 + 2][j] = v.z;
            s.ksT[c4 * 4 + 3][j] = v.w;
        }
        const float4* gp4 = (const float4*)g_negPj;
        for (int t = tid; t < TJ * 16; t += 256) {
            int j = t >> 4, m4 = t & 15;
            float4 v = gp4[(j0 + j) * 16 + m4];
            s.nPjT[m4 * 4 + 0][j] = v.x;
            s.nPjT[m4 * 4 + 1][j] = v.y;
            s.nPjT[m4 * 4 + 2][j] = v.z;
            s.nPjT[m4 * 4 + 3][j] = v.w;
        }
    }
    for (int t = tid; t < TI * HID; t += 256) {
        int r = t >> 6, m = t & 63;
        s.Pib[r][m] = g_Pib[(i0 + r) * HID + m];
        s.A4[r][m]  = g_A4[(i0 + r) * HID + m];
    }
    if (tid < TI) {
        s.pis[tid][0] = pos[(i0 + tid) * 3 + 0];
        s.pis[tid][1] = pos[(i0 + tid) * 3 + 1];
        s.pis[tid][2] = pos[(i0 + tid) * 3 + 2];
    }
    if (tid < TJ) {
        s.pjs[tid][0] = pos[(j0 + tid) * 3 + 0];
        s.pjs[tid][1] = pos[(j0 + tid) * 3 + 1];
        s.pjs[tid][2] = pos[(j0 + tid) * 3 + 2];
    }
    if (tid < TI * H) {
        s.qb2[tid >> 2][tid & 3] = g_qb2[(i0 + (tid >> 2)) * H + (tid & 3)];
    }
    __syncthreads();

    int il = tid >> 4;
    int jt = tid & 15;
    int ia = il, ib = il + 16;
    int jc0 = 2 * jt;
    int jc1 = 2 * jt + 32;

    u64 acc[2][4][2];
#pragma unroll
    for (int h = 0; h < 4; h++) {
        float qa = s.qb2[ia][h], qb = s.qb2[ib][h];
        u64 ta, tb;
        PACK2(ta, qa, qa); PACK2(tb, qb, qb);
        acc[0][h][0] = ta; acc[0][h][1] = ta;
        acc[1][h][0] = tb; acc[1][h][1] = tb;
    }

#pragma unroll 4
    for (int m = 0; m < HID; m++) {
        float pa = s.Pib[ia][m], pb = s.Pib[ib][m];
        u64 pa2, pb2;
        PACK2(pa2, pa, pa); PACK2(pb2, pb, pb);
        u64 n0 = *(const u64*)&s.nPjT[m][jc0];
        u64 n1 = *(const u64*)&s.nPjT[m][jc1];

        u64 za0, za1, zb0, zb1;
        ADD2(za0, pa2, n0); ADD2(za1, pa2, n1);
        ADD2(zb0, pb2, n0); ADD2(zb1, pb2, n1);

        float lo, hi;
        u64 ha0, ha1, hb0, hb1;
        UNPACK2(lo, hi, za0); PACK2(ha0, fmaxf(lo, 0.f), fmaxf(hi, 0.f));
        UNPACK2(lo, hi, za1); PACK2(ha1, fmaxf(lo, 0.f), fmaxf(hi, 0.f));
        UNPACK2(lo, hi, zb0); PACK2(hb0, fmaxf(lo, 0.f), fmaxf(hi, 0.f));
        UNPACK2(lo, hi, zb1); PACK2(hb1, fmaxf(lo, 0.f), fmaxf(hi, 0.f));

        float4 aa = s.A4[ia][m], ab = s.A4[ib][m];
        u64 ax, ay, az, aw, bx, by, bz, bw;
        PACK2(ax, aa.x, aa.x); PACK2(ay, aa.y, aa.y);
        PACK2(az, aa.z, aa.z); PACK2(aw, aa.w, aa.w);
        PACK2(bx, ab.x, ab.x); PACK2(by, ab.y, ab.y);
        PACK2(bz, ab.z, ab.z); PACK2(bw, ab.w, ab.w);

        FMA2(acc[0][0][0], ha0, ax); FMA2(acc[0][0][1], ha1, ax);
        FMA2(acc[0][1][0], ha0, ay); FMA2(acc[0][1][1], ha1, ay);
        FMA2(acc[0][2][0], ha0, az); FMA2(acc[0][2][1], ha1, az);
        FMA2(acc[0][3][0], ha0, aw); FMA2(acc[0][3][1], ha1, aw);
        FMA2(acc[1][0][0], hb0, bx); FMA2(acc[1][0][1], hb1, bx);
        FMA2(acc[1][1][0], hb0, by); FMA2(acc[1][1][1], hb1, by);
        FMA2(acc[1][2][0], hb0, bz); FMA2(acc[1][2][1], hb1, bz);
        FMA2(acc[1][3][0], hb0, bw); FMA2(acc[1][3][1], hb1, bw);
    }

#pragma unroll
    for (int h = 0; h < 4; h++) {
#pragma unroll
        for (int d2 = 0; d2 < 16; d2++) {
            int c = h * HD + 2 * d2;
            float2 qa = *(const float2*)&s.qs[ia][c];
            float2 qb = *(const float2*)&s.qs[ib][c];
            u64 k00 = *(const u64*)&s.ksT[c][jc0];
            u64 k01 = *(const u64*)&s.ksT[c][jc1];
            u64 k10 = *(const u64*)&s.ksT[c + 1][jc0];
            u64 k11 = *(const u64*)&s.ksT[c + 1][jc1];
            u64 qa0, qa1, qb0, qb1;
            PACK2(qa0, qa.x, qa.x); PACK2(qa1, qa.y, qa.y);
            PACK2(qb0, qb.x, qb.x); PACK2(qb1, qb.y, qb.y);
            FMA2(acc[0][h][0], qa0, k00); FMA2(acc[0][h][1], qa0, k01);
            FMA2(acc[0][h][0], qa1, k10); FMA2(acc[0][h][1], qa1, k11);
            FMA2(acc[1][h][0], qb0, k00); FMA2(acc[1][h][1], qb0, k01);
            FMA2(acc[1][h][0], qb1, k10); FMA2(acc[1][h][1], qb1, k11);
        }
    }

    float pax = s.pis[ia][0], pay = s.pis[ia][1], paz = s.pis[ia][2];
    float pbx = s.pis[ib][0], pby = s.pis[ib][1], pbz = s.pis[ib][2];
    float da[2][2], db[2][2];
#pragma unroll
    for (int p = 0; p < 2; p++) {
        int jc = (p == 0) ? jc0 : jc1;
#pragma unroll
        for (int e = 0; e < 2; e++) {
            int j = jc + e;
            float jx = s.pjs[j][0], jy = s.pjs[j][1], jz = s.pjs[j][2];
            float x0 = pax - jx, y0_ = pay - jy, z0 = paz - jz;
            float x1 = pbx - jx, y1_ = pby - jy, z1 = pbz - jz;
            da[p][e] = sqrtf(x0 * x0 + y0_ * y0_ + z0 * z0);
            db[p][e] = sqrtf(x1 * x1 + y1_ * y1_ + z1 * z1);
        }
    }

    int iga = i0 + ia, igb = i0 + ib;
#pragma unroll
    for (int h = 0; h < 4; h++) {
        size_t basea = ((size_t)h * N + iga) * N + j0;
        size_t baseb = ((size_t)h * N + igb) * N + j0;
#pragma unroll
        for (int p = 0; p < 2; p++) {
            int jc = (p == 0) ? jc0 : jc1;
            float lo, hi;
            UNPACK2(lo, hi, acc[0][h][p]);
            float2 sca = make_float2(lo - da[p][0], hi - da[p][1]);
            UNPACK2(lo, hi, acc[1][h][p]);
            float2 scb = make_float2(lo - db[p][0], hi - db[p][1]);
            *(float2*)&g_scores[basea + jc] = sca;
            *(float2*)&g_scores[baseb + jc] = scb;
        }
    }
}

// ---------------------------------------------------------------
// K4 v2: softmax + PV. grid (N/8, H), block 128 (4 warps).
// Phase 1: warp w -> rows {w, w+4}. Phase 2: warp w -> 256-wide j
// slice, lane = d, f32x2-packed over j-pairs, LDS.128 es loads.
// ---------------------------------------------------------------
struct SoftmaxSmem {
    float es[8][1032];        // row stride 1032 (16B-aligned rows)
    float red[4][8][33];
    float inv_sum[8];
};

__global__ void __launch_bounds__(128) softmax_out_kernel(float* __restrict__ out) {
    extern __shared__ __align__(16) char s_raw[];
    SoftmaxSmem& s = *reinterpret_cast<SoftmaxSmem*>(s_raw);

    int h = blockIdx.y;
    int i0 = blockIdx.x * 8;
    int warp = threadIdx.x >> 5, lane = threadIdx.x & 31;

    // ---- phase 1: softmax numerator for rows {warp, warp+4} ----
#pragma unroll
    for (int rr = 0; rr < 2; rr++) {
        int r = warp + rr * 4;
        int i = i0 + r;
        const float4* srow = (const float4*)(g_scores + ((size_t)h * N + i) * N);

        float4 xv[8];
        float m = -INFINITY;
#pragma unroll
        for (int t = 0; t < 8; t++) {
            xv[t] = srow[t * 32 + lane];
            m = fmaxf(m, fmaxf(fmaxf(xv[t].x, xv[t].y), fmaxf(xv[t].z, xv[t].w)));
        }
#pragma unroll
        for (int o = 16; o; o >>= 1) m = fmaxf(m, __shfl_xor_sync(0xFFFFFFFFu, m, o));

        float sum = 0.f;
#pragma unroll
        for (int t = 0; t < 8; t++) {
            float4 e;
            e.x = __expf(xv[t].x - m);
            e.y = __expf(xv[t].y - m);
            e.z = __expf(xv[t].z - m);
            e.w = __expf(xv[t].w - m);
            *(float4*)&s.es[r][t * 128 + lane * 4] = e;
            sum += (e.x + e.y) + (e.z + e.w);
        }
#pragma unroll
        for (int o = 16; o; o >>= 1) sum += __shfl_xor_sync(0xFFFFFFFFu, sum, o);
        if (lane == 0) s.inv_sum[r] = 1.0f / sum;
    }
    __syncthreads();

    // ---- phase 2: PV, packed over j-pairs; lane owns column d ----
    u64 acc[8];
    {
        u64 z; PACK2(z, 0.f, 0.f);
#pragma unroll
        for (int r = 0; r < 8; r++) acc[r] = z;
    }

    const float* vb = g_v + h * HD + lane;  // column d = lane
    int jbase = warp * 256;
#pragma unroll 2
    for (int j = jbase; j < jbase + 256; j += 4) {
        float v0 = vb[(j + 0) * C];
        float v1 = vb[(j + 1) * C];
        float v2 = vb[(j + 2) * C];
        float v3 = vb[(j + 3) * C];
        u64 v01, v23;
        PACK2(v01, v0, v1); PACK2(v23, v2, v3);
#pragma unroll
        for (int r = 0; r < 8; r++) {
            float4 e4 = *(const float4*)&s.es[r][j];
            u64 e01, e23;
            PACK2(e01, e4.x, e4.y); PACK2(e23, e4.z, e4.w);
            FMA2(acc[r], e01, v01);
            FMA2(acc[r], e23, v23);
        }
    }
#pragma unroll
    for (int r = 0; r < 8; r++) {
        float lo, hi;
        UNPACK2(lo, hi, acc[r]);
        s.red[warp][r][lane] = lo + hi;
    }
    __syncthreads();

    // ---- cross-warp reduce + writeback: 256 outputs, 2/thread ----
#pragma unroll
    for (int o = threadIdx.x; o < 256; o += 128) {
        int r = o >> 5, d = o & 31;
        float v = (s.red[0][r][d] + s.red[1][r][d]) + (s.red[2][r][d] + s.red[3][r][d]);
        out[(i0 + r) * C + h * HD + d] = v * s.inv_sum[r];
    }
}

// ---------------------------------------------------------------
extern "C" void kernel_launch(void* const* d_in, const int* in_sizes, int n_in,
                              void* d_out, int out_size) {
    (void)in_sizes; (void)n_in; (void)out_size;
    const float* x   = (const float*)d_in[0];
    const float* y   = (const float*)d_in[1];
    const float* pos = (const float*)d_in[2];
    const float* Wq  = (const float*)d_in[3];
    const float* bq  = (const float*)d_in[4];
    const float* Wk  = (const float*)d_in[5];
    const float* bk  = (const float*)d_in[6];
    const float* Wv  = (const float*)d_in[7];
    const float* bv  = (const float*)d_in[8];
    const float* W1  = (const float*)d_in[9];
    const float* b1  = (const float*)d_in[10];
    const float* W2  = (const float*)d_in[11];
    const float* b2  = (const float*)d_in[12];
    float* out = (float*)d_out;

    static bool attrs_set = false;
    if (!attrs_set) {
        cudaFuncSetAttribute(scores_kernel, cudaFuncAttributeMaxDynamicSharedMemorySize,
                             (int)sizeof(ScoresSmem));
        cudaFuncSetAttribute(softmax_out_kernel, cudaFuncAttributeMaxDynamicSharedMemorySize,
                             (int)sizeof(SoftmaxSmem));
        attrs_set = true;
    }

    qkv_prep_kernel<<<dim3(N / 16, 3), 128>>>(x, y, pos, Wq, bq, Wk, bk, Wv, bv,
                                              W1, b1, W2, b2);
    scores_kernel<<<dim3(N / TJ, N / TI), 256, sizeof(ScoresSmem)>>>(pos);
    softmax_out_kernel<<<dim3(N / 8, H), 128, sizeof(SoftmaxSmem)>>>(out);
}